// round 9
// baseline (speedup 1.0000x reference)
#include <cuda_runtime.h>
#include <cstdint>

// JAX threefry (partitionable), bit-exact draws confirmed (rel_err ~5e-8).
// R7: balanced worklist (113.4us). R8: IMAD rotations — regression, reverted.
// R9: occupancy push — __launch_bounds__(256,5) (~51 reg cap), all frame
//     unrolls removed (halves live state). Theory: issue fell 80%->46% from
//     register-pressure occupancy collapse, not pipe saturation.

static constexpr int Bn   = 8;
static constexpr int Cn   = 5;
static constexpr int FMAX = 16;
static constexpr int HW   = 512 * 512;        // 2^18
static constexpr int NPIX = Bn * HW;          // 2^21

__device__ float g_bias[Bn];
__device__ float g_part[512];

// ---------------------------------------------------------------------------
__device__ __forceinline__ float f_lg2(float x) { float r; asm("lg2.approx.f32 %0,%1;"  : "=f"(r) : "f"(x)); return r; }
__device__ __forceinline__ float f_ex2(float x) { float r; asm("ex2.approx.f32 %0,%1;"  : "=f"(r) : "f"(x)); return r; }
__device__ __forceinline__ float f_sqa(float x) { float r; asm("sqrt.approx.f32 %0,%1;" : "=f"(r) : "f"(x)); return r; }
__device__ __forceinline__ float clip01(float x) { return fminf(fmaxf(x, 0.0f), 1.0f); }

// Threefry-2x32, 20 rounds; counter (0, j); returns x0 ^ x1 (partitionable fold)
__device__ __forceinline__ uint32_t tf_xor(uint32_t k0, uint32_t k1, uint32_t j) {
    uint32_t k2 = k0 ^ k1 ^ 0x1BD11BDAu;
    uint32_t x0 = k0;
    uint32_t x1 = j + k1;
#define TFR(r) { x0 += x1; x1 = __funnelshift_l(x1, x1, (r)); x1 ^= x0; }
    TFR(13) TFR(15) TFR(26) TFR(6)   x0 += k1; x1 += k2 + 1u;
    TFR(17) TFR(29) TFR(16) TFR(24)  x0 += k2; x1 += k0 + 2u;
    TFR(13) TFR(15) TFR(26) TFR(6)   x0 += k0; x1 += k1 + 3u;
    TFR(17) TFR(29) TFR(16) TFR(24)  x0 += k1; x1 += k2 + 4u;
    TFR(13) TFR(15) TFR(26) TFR(6)   x0 += k2; x1 += k0 + 5u;
#undef TFR
    return x0 ^ x1;
}

// uniform-bits -> (-log u)^(-fa)  (bit-validated R3/R5)
__device__ __forceinline__ float u_term(uint32_t ub, float nfa) {
    float su = (float)(ub >> 9);
    float u  = su * 1.1920928955078125e-7f;            // * 2^-23 exact
    u = fminf(fmaxf(u, 1e-6f), 0.999999f);
    float tA = f_lg2(u) * -0.693147180559945f;         // MUFU path
    float v  = u - 1.0f;                               // exact for u >= 0.5
    float P  = fmaf(v, 0.14285714f, -0.16666667f);
    P = fmaf(P, v, 0.20f);
    P = fmaf(P, v, -0.25f);
    P = fmaf(P, v, 0.33333333f);
    P = fmaf(P, v, -0.5f);
    P = fmaf(P, v, 1.0f);
    float tB = -(v * P);                               // log1p Taylor near 1
    float t  = (u >= 0.875f) ? tB : tA;
    return f_ex2(nfa * f_lg2(t));                      // t^(-fa)
}

// normal-bits -> erfinv(g); caller supplies sqrt(2) inside vgs = gw*sqrt2
__device__ __forceinline__ float n_term(uint32_t nb) {
    const float LO = -0.99999994f;                     // nextafter(-1, 0)
    float sn = (float)(nb >> 9);
    float gx = fmaf(sn, 2.384185791015625e-7f, LO);    // * 2^-22 exact
    float W  = f_lg2(fmaf(-gx, gx, 1.0f));             // lg2(1-gx^2), <= 0
    float pe;
    if (W > -7.21347520444482f) {                      // w = -ln2*W < 5
        float z = fmaf(-0.693147180559945f, W, -2.5f); // z = w - 2.5
        pe = 2.81022636e-08f;
        pe = fmaf(pe, z, 3.43273939e-07f);
        pe = fmaf(pe, z, -3.5233877e-06f);
        pe = fmaf(pe, z, -4.39150654e-06f);
        pe = fmaf(pe, z, 0.00021858087f);
        pe = fmaf(pe, z, -0.00125372503f);
        pe = fmaf(pe, z, -0.00417768164f);
        pe = fmaf(pe, z, 0.246640727f);
        pe = fmaf(pe, z, 1.50140941f);
    } else {
        float w = W * -0.693147180559945f;
        float z = f_sqa(w) - 3.0f;
        pe = -0.000200214257f;
        pe = fmaf(pe, z, 0.000100950558f);
        pe = fmaf(pe, z, 0.00134934322f);
        pe = fmaf(pe, z, -0.00367342844f);
        pe = fmaf(pe, z, 0.00573950773f);
        pe = fmaf(pe, z, -0.0076224613f);
        pe = fmaf(pe, z, 0.00943887047f);
        pe = fmaf(pe, z, 1.00167406f);
        pe = fmaf(pe, z, 2.83297682f);
    }
    return pe * gx;                                    // erfinv(gx)
}

// ---------------------------------------------------------------------------
// Bias stage 1: 512 blocks (64/batch) x 256 threads, 4 strided float4 (MLP=4)
// ---------------------------------------------------------------------------
__global__ void __launch_bounds__(256) bias_partial(const float* __restrict__ in) {
    int b     = blockIdx.x >> 6;
    int chunk = blockIdx.x & 63;
    int t     = threadIdx.x;
    const float4* p4 = reinterpret_cast<const float4*>(in + ((size_t)b * Cn + 1) * HW)
                     + (size_t)chunk * 1024;
    float4 a = p4[t], b4 = p4[t + 256], c = p4[t + 512], d = p4[t + 768];
    float s = ((a.x + a.y) + (a.z + a.w)) + ((b4.x + b4.y) + (b4.z + b4.w))
            + ((c.x + c.y) + (c.z + c.w)) + ((d.x + d.y) + (d.z + d.w));
    __shared__ float sm[8];
    #pragma unroll
    for (int o = 16; o > 0; o >>= 1) s += __shfl_down_sync(0xffffffffu, s, o);
    if ((t & 31) == 0) sm[t >> 5] = s;
    __syncthreads();
    if (t == 0) {
        float acc = 0.0f;
        #pragma unroll
        for (int k = 0; k < 8; k++) acc += sm[k];
        g_part[blockIdx.x] = acc;
    }
}

// Bias stage 2: one block; warp b reduces its 64 partials in fixed order
__global__ void __launch_bounds__(256) bias_final() {
    int b = threadIdx.x >> 5, l = threadIdx.x & 31;
    float v = g_part[b * 64 + l] + g_part[b * 64 + 32 + l];
    #pragma unroll
    for (int o = 16; o > 0; o >>= 1) v += __shfl_down_sync(0xffffffffu, v, o);
    if (l == 0) g_bias[b] = fmaxf(v * (1.0f / (float)HW), 0.0f);
}

// ---------------------------------------------------------------------------
// Main kernel: classify -> balanced compaction -> uniform-work frame loops
// Segments: [Blo(nB) | Bhi(nB) | U(nU) | N(nN)]
// ---------------------------------------------------------------------------
__global__ void __launch_bounds__(256, 5)
acq_kernel(const float* __restrict__ in, const int* __restrict__ frames,
           float* __restrict__ out,
           uint32_t ku0, uint32_t ku1, uint32_t kn0, uint32_t kn1) {
    __shared__ float4 stash[256];
    __shared__ unsigned short wl[512];
    __shared__ float partA[256];
    __shared__ float partB[256];
    __shared__ int segcnt[3];   // [B, U, N]
    __shared__ int place[3];

    const int t     = threadIdx.x;
    const int b     = blockIdx.x & 7;              // batch-interleaved remap
    const int chunk = blockIdx.x >> 3;
    const int p0    = chunk * 256;                 // pixel base within batch
    const int gpix  = b * HW + p0;

    const float* base = in + (size_t)b * Cn * HW + (p0 + t);
    float img = base[0];
    float fw  = fmaxf(base[2 * HW], 0.0f);
    float fa  = fmaxf(base[3 * HW], 0.0f);
    float gw  = fmaxf(base[4 * HW], 0.0f);
    float bias = g_bias[b];
    const int nf = frames[b];                      // uniform across block
    const int hf = (nf + 1) >> 1;                  // frame split point

    float cb  = img + bias;
    float nfa = -fa;
    float gs  = gw * 1.41421356237f;               // gw * sqrt(2)

    // center (all pixels)
    float cpw = f_ex2(nfa * f_lg2(fa + 1.0f));
    out[NPIX + gpix + t] = clip01(fmaf(fw, cpw, cb));

    // classification
    bool needU = (fw > 0.0f) && (fa > 0.0f);
    bool needN = (gw > 0.0f);
    int  cat   = needU ? (needN ? 0 : 1) : (needN ? 2 : 3);
    float cbase = (cat >= 2) ? (cb + ((fa == 0.0f) ? fw : 0.0f)) : cb;

    if (cat == 3) out[gpix + t] = clip01(cbase);   // deterministic: done

    stash[t] = make_float4(cbase, fw, nfa, gs);

    if (t < 3) segcnt[t] = 0;
    __syncthreads();

    unsigned m0 = __ballot_sync(0xffffffffu, cat == 0);
    unsigned m1 = __ballot_sync(0xffffffffu, cat == 1);
    unsigned m2 = __ballot_sync(0xffffffffu, cat == 2);
    if ((t & 31) == 0) {
        if (m0) atomicAdd(&segcnt[0], __popc(m0));
        if (m1) atomicAdd(&segcnt[1], __popc(m1));
        if (m2) atomicAdd(&segcnt[2], __popc(m2));
    }
    __syncthreads();
    const int nB = segcnt[0], nU = segcnt[1], nN = segcnt[2];
    if (t == 0) {
        place[0] = 0;                              // Blo ranks 0..nB-1
        place[1] = 2 * nB;                         // U base
        place[2] = 2 * nB + nU;                    // N base
    }
    __syncthreads();

    unsigned lanelt = (1u << (t & 31)) - 1u;
    if (cat == 0) {
        int ldr = __ffs(m0) - 1, bse = 0;
        if ((t & 31) == ldr) bse = atomicAdd(&place[0], __popc(m0));
        bse = __shfl_sync(m0, bse, ldr);
        int r = bse + __popc(m0 & lanelt);
        wl[r]      = (unsigned short)t;            // Blo entry
        wl[nB + r] = (unsigned short)t;            // Bhi entry (pair)
    } else if (cat == 1) {
        int ldr = __ffs(m1) - 1, bse = 0;
        if ((t & 31) == ldr) bse = atomicAdd(&place[1], __popc(m1));
        bse = __shfl_sync(m1, bse, ldr);
        wl[bse + __popc(m1 & lanelt)] = (unsigned short)t;
    } else if (cat == 2) {
        int ldr = __ffs(m2) - 1, bse = 0;
        if ((t & 31) == ldr) bse = atomicAdd(&place[2], __popc(m2));
        bse = __shfl_sync(m2, bse, ldr);
        wl[bse + __popc(m2 & lanelt)] = (unsigned short)t;
    }
    __syncthreads();

    const int total = 2 * nB + nU + nN;

    for (int e = t; e < total; e += 256) {
        int lp = wl[e];
        float4 v = stash[lp];
        float vb = v.x, vfw = v.y, vnfa = v.z, vgs = v.w;
        uint32_t jb = (uint32_t)(b * FMAX) * (uint32_t)HW + (uint32_t)(p0 + lp);
        float acc = 0.0f;

        if (e < 2 * nB) {
            // both streams over half frame range (balanced: ~nf tf calls)
            bool lo = (e < nB);
            int f0 = lo ? 0 : hf;
            int f1 = lo ? hf : nf;
            uint32_t j = jb + (uint32_t)f0 * (uint32_t)HW;
            for (int f = f0; f < f1; ++f, j += (uint32_t)HW) {
                uint32_t ub = tf_xor(ku0, ku1, j);
                uint32_t nb = tf_xor(kn0, kn1, j);
                float s = fmaf(vfw, u_term(ub, vnfa), vb);
                s = fmaf(vgs, n_term(nb), s);
                acc += clip01(s);
            }
            if (lo) partA[e] = acc; else partB[e - nB] = acc;
        } else if (e < 2 * nB + nU) {
            // uniform-only, full range
            uint32_t j = jb;
            for (int f = 0; f < nf; ++f, j += (uint32_t)HW) {
                uint32_t u0 = tf_xor(ku0, ku1, j);
                acc += clip01(fmaf(vfw, u_term(u0, vnfa), vb));
            }
            out[gpix + lp] = acc / (float)nf;
        } else {
            // normal-only, full range
            uint32_t j = jb;
            for (int f = 0; f < nf; ++f, j += (uint32_t)HW) {
                uint32_t n0 = tf_xor(kn0, kn1, j);
                acc += clip01(fmaf(vgs, n_term(n0), vb));
            }
            out[gpix + lp] = acc / (float)nf;
        }
    }

    __syncthreads();

    for (int i = t; i < nB; i += 256) {
        int lp = wl[i];
        out[gpix + lp] = (partA[i] + partB[i]) / (float)nf;
    }
}

// ---------------------------------------------------------------------------
// Host-side threefry for key derivation from jax.random.key(42)
// ---------------------------------------------------------------------------
static inline uint32_t h_rotl(uint32_t x, int r) { return (x << r) | (x >> (32 - r)); }
static void h_tf2x32(uint32_t k0, uint32_t k1, uint32_t x0, uint32_t x1,
                     uint32_t& o0, uint32_t& o1) {
    uint32_t k2 = k0 ^ k1 ^ 0x1BD11BDAu;
    x0 += k0; x1 += k1;
#define HTFR(r) { x0 += x1; x1 = h_rotl(x1, (r)); x1 ^= x0; }
    HTFR(13) HTFR(15) HTFR(26) HTFR(6)   x0 += k1; x1 += k2 + 1u;
    HTFR(17) HTFR(29) HTFR(16) HTFR(24)  x0 += k2; x1 += k0 + 2u;
    HTFR(13) HTFR(15) HTFR(26) HTFR(6)   x0 += k0; x1 += k1 + 3u;
    HTFR(17) HTFR(29) HTFR(16) HTFR(24)  x0 += k1; x1 += k2 + 4u;
    HTFR(13) HTFR(15) HTFR(26) HTFR(6)   x0 += k2; x1 += k0 + 5u;
#undef HTFR
    o0 = x0; o1 = x1;
}

extern "C" void kernel_launch(void* const* d_in, const int* in_sizes, int n_in,
                              void* d_out, int out_size) {
    const float* inp    = (const float*)d_in[0];
    const int*   frames = (const int*)d_in[1];
    float*       out    = (float*)d_out;

    uint32_t ku0, ku1, kn0, kn1;
    h_tf2x32(0u, 42u, 0u, 0u, ku0, ku1);
    h_tf2x32(0u, 42u, 0u, 1u, kn0, kn1);

    bias_partial<<<512, 256>>>(inp);
    bias_final<<<1, 256>>>();
    acq_kernel<<<NPIX / 256, 256>>>(inp, frames, out, ku0, ku1, kn0, kn1);
}

// round 10
// speedup vs baseline: 1.1291x; 1.1291x over previous
#include <cuda_runtime.h>
#include <cstdint>

// JAX threefry (partitionable), bit-exact draws confirmed (rel_err ~5e-8).
// R7: balanced worklist (113.4us). R8/R9: pipe/occupancy theories — neutral.
// R10: warp-aligned worklist segments. Boundary warps were executing TWO
//      segment bodies serially (masked divergence); padding each segment to a
//      32-entry boundary guarantees one body per warp. Gaps = sentinel lanes.

static constexpr int Bn   = 8;
static constexpr int Cn   = 5;
static constexpr int FMAX = 16;
static constexpr int HW   = 512 * 512;        // 2^18
static constexpr int NPIX = Bn * HW;          // 2^21
static constexpr unsigned short SENT = 0xFFFFu;

__device__ float g_bias[Bn];
__device__ float g_part[512];

// ---------------------------------------------------------------------------
__device__ __forceinline__ float f_lg2(float x) { float r; asm("lg2.approx.f32 %0,%1;"  : "=f"(r) : "f"(x)); return r; }
__device__ __forceinline__ float f_ex2(float x) { float r; asm("ex2.approx.f32 %0,%1;"  : "=f"(r) : "f"(x)); return r; }
__device__ __forceinline__ float f_sqa(float x) { float r; asm("sqrt.approx.f32 %0,%1;" : "=f"(r) : "f"(x)); return r; }
__device__ __forceinline__ float clip01(float x) { return fminf(fmaxf(x, 0.0f), 1.0f); }

// Threefry-2x32, 20 rounds; counter (0, j); returns x0 ^ x1 (partitionable fold)
__device__ __forceinline__ uint32_t tf_xor(uint32_t k0, uint32_t k1, uint32_t j) {
    uint32_t k2 = k0 ^ k1 ^ 0x1BD11BDAu;
    uint32_t x0 = k0;
    uint32_t x1 = j + k1;
#define TFR(r) { x0 += x1; x1 = __funnelshift_l(x1, x1, (r)); x1 ^= x0; }
    TFR(13) TFR(15) TFR(26) TFR(6)   x0 += k1; x1 += k2 + 1u;
    TFR(17) TFR(29) TFR(16) TFR(24)  x0 += k2; x1 += k0 + 2u;
    TFR(13) TFR(15) TFR(26) TFR(6)   x0 += k0; x1 += k1 + 3u;
    TFR(17) TFR(29) TFR(16) TFR(24)  x0 += k1; x1 += k2 + 4u;
    TFR(13) TFR(15) TFR(26) TFR(6)   x0 += k2; x1 += k0 + 5u;
#undef TFR
    return x0 ^ x1;
}

// uniform-bits -> (-log u)^(-fa)  (bit-validated R3/R5)
__device__ __forceinline__ float u_term(uint32_t ub, float nfa) {
    float su = (float)(ub >> 9);
    float u  = su * 1.1920928955078125e-7f;            // * 2^-23 exact
    u = fminf(fmaxf(u, 1e-6f), 0.999999f);
    float tA = f_lg2(u) * -0.693147180559945f;         // MUFU path
    float v  = u - 1.0f;                               // exact for u >= 0.5
    float P  = fmaf(v, 0.14285714f, -0.16666667f);
    P = fmaf(P, v, 0.20f);
    P = fmaf(P, v, -0.25f);
    P = fmaf(P, v, 0.33333333f);
    P = fmaf(P, v, -0.5f);
    P = fmaf(P, v, 1.0f);
    float tB = -(v * P);                               // log1p Taylor near 1
    float t  = (u >= 0.875f) ? tB : tA;
    return f_ex2(nfa * f_lg2(t));                      // t^(-fa)
}

// normal-bits -> erfinv(g); caller supplies sqrt(2) inside vgs = gw*sqrt2
__device__ __forceinline__ float n_term(uint32_t nb) {
    const float LO = -0.99999994f;                     // nextafter(-1, 0)
    float sn = (float)(nb >> 9);
    float gx = fmaf(sn, 2.384185791015625e-7f, LO);    // * 2^-22 exact
    float W  = f_lg2(fmaf(-gx, gx, 1.0f));             // lg2(1-gx^2), <= 0
    float pe;
    if (W > -7.21347520444482f) {                      // w = -ln2*W < 5
        float z = fmaf(-0.693147180559945f, W, -2.5f); // z = w - 2.5
        pe = 2.81022636e-08f;
        pe = fmaf(pe, z, 3.43273939e-07f);
        pe = fmaf(pe, z, -3.5233877e-06f);
        pe = fmaf(pe, z, -4.39150654e-06f);
        pe = fmaf(pe, z, 0.00021858087f);
        pe = fmaf(pe, z, -0.00125372503f);
        pe = fmaf(pe, z, -0.00417768164f);
        pe = fmaf(pe, z, 0.246640727f);
        pe = fmaf(pe, z, 1.50140941f);
    } else {
        float w = W * -0.693147180559945f;
        float z = f_sqa(w) - 3.0f;
        pe = -0.000200214257f;
        pe = fmaf(pe, z, 0.000100950558f);
        pe = fmaf(pe, z, 0.00134934322f);
        pe = fmaf(pe, z, -0.00367342844f);
        pe = fmaf(pe, z, 0.00573950773f);
        pe = fmaf(pe, z, -0.0076224613f);
        pe = fmaf(pe, z, 0.00943887047f);
        pe = fmaf(pe, z, 1.00167406f);
        pe = fmaf(pe, z, 2.83297682f);
    }
    return pe * gx;                                    // erfinv(gx)
}

// ---------------------------------------------------------------------------
// Bias stage 1: 512 blocks (64/batch) x 256 threads, 4 strided float4 (MLP=4)
// ---------------------------------------------------------------------------
__global__ void __launch_bounds__(256) bias_partial(const float* __restrict__ in) {
    int b     = blockIdx.x >> 6;
    int chunk = blockIdx.x & 63;
    int t     = threadIdx.x;
    const float4* p4 = reinterpret_cast<const float4*>(in + ((size_t)b * Cn + 1) * HW)
                     + (size_t)chunk * 1024;
    float4 a = p4[t], b4 = p4[t + 256], c = p4[t + 512], d = p4[t + 768];
    float s = ((a.x + a.y) + (a.z + a.w)) + ((b4.x + b4.y) + (b4.z + b4.w))
            + ((c.x + c.y) + (c.z + c.w)) + ((d.x + d.y) + (d.z + d.w));
    __shared__ float sm[8];
    #pragma unroll
    for (int o = 16; o > 0; o >>= 1) s += __shfl_down_sync(0xffffffffu, s, o);
    if ((t & 31) == 0) sm[t >> 5] = s;
    __syncthreads();
    if (t == 0) {
        float acc = 0.0f;
        #pragma unroll
        for (int k = 0; k < 8; k++) acc += sm[k];
        g_part[blockIdx.x] = acc;
    }
}

// Bias stage 2: one block; warp b reduces its 64 partials in fixed order
__global__ void __launch_bounds__(256) bias_final() {
    int b = threadIdx.x >> 5, l = threadIdx.x & 31;
    float v = g_part[b * 64 + l] + g_part[b * 64 + 32 + l];
    #pragma unroll
    for (int o = 16; o > 0; o >>= 1) v += __shfl_down_sync(0xffffffffu, v, o);
    if (l == 0) g_bias[b] = fmaxf(v * (1.0f / (float)HW), 0.0f);
}

// ---------------------------------------------------------------------------
// Main kernel: classify -> warp-aligned compaction -> one body per warp
// Layout: [B: 0..2nB) | pad | U: baseU..baseU+nU) | pad | N: baseN..baseN+nN)
// ---------------------------------------------------------------------------
__global__ void __launch_bounds__(256)
acq_kernel(const float* __restrict__ in, const int* __restrict__ frames,
           float* __restrict__ out,
           uint32_t ku0, uint32_t ku1, uint32_t kn0, uint32_t kn1) {
    __shared__ float4 stash[256];
    __shared__ unsigned short wl[576];
    __shared__ float partA[256];
    __shared__ float partB[256];
    __shared__ int segcnt[3];   // [B, U, N]
    __shared__ int place[3];

    const int t     = threadIdx.x;
    const int b     = blockIdx.x & 7;              // batch-interleaved remap
    const int chunk = blockIdx.x >> 3;
    const int p0    = chunk * 256;                 // pixel base within batch
    const int gpix  = b * HW + p0;

    const float* base = in + (size_t)b * Cn * HW + (p0 + t);
    float img = base[0];
    float fw  = fmaxf(base[2 * HW], 0.0f);
    float fa  = fmaxf(base[3 * HW], 0.0f);
    float gw  = fmaxf(base[4 * HW], 0.0f);
    float bias = g_bias[b];
    const int nf = frames[b];                      // uniform across block
    const int hf = (nf + 1) >> 1;                  // frame split point

    float cb  = img + bias;
    float nfa = -fa;
    float gs  = gw * 1.41421356237f;               // gw * sqrt(2)

    // center (all pixels)
    float cpw = f_ex2(nfa * f_lg2(fa + 1.0f));
    out[NPIX + gpix + t] = clip01(fmaf(fw, cpw, cb));

    // classification
    bool needU = (fw > 0.0f) && (fa > 0.0f);
    bool needN = (gw > 0.0f);
    int  cat   = needU ? (needN ? 0 : 1) : (needN ? 2 : 3);
    float cbase = (cat >= 2) ? (cb + ((fa == 0.0f) ? fw : 0.0f)) : cb;

    if (cat == 3) out[gpix + t] = clip01(cbase);   // deterministic: done

    stash[t] = make_float4(cbase, fw, nfa, gs);

    // clear sentinel worklist (576 entries)
    wl[t] = SENT; wl[t + 256] = SENT;
    if (t < 64) wl[t + 512] = SENT;
    if (t < 3) segcnt[t] = 0;
    __syncthreads();

    unsigned m0 = __ballot_sync(0xffffffffu, cat == 0);
    unsigned m1 = __ballot_sync(0xffffffffu, cat == 1);
    unsigned m2 = __ballot_sync(0xffffffffu, cat == 2);
    if ((t & 31) == 0) {
        if (m0) atomicAdd(&segcnt[0], __popc(m0));
        if (m1) atomicAdd(&segcnt[1], __popc(m1));
        if (m2) atomicAdd(&segcnt[2], __popc(m2));
    }
    __syncthreads();
    const int nB = segcnt[0], nU = segcnt[1], nN = segcnt[2];
    const int baseU = (2 * nB + 31) & ~31;         // warp-aligned U base
    const int baseN = (baseU + nU + 31) & ~31;     // warp-aligned N base
    if (t == 0) {
        place[0] = 0;
        place[1] = baseU;
        place[2] = baseN;
    }
    __syncthreads();

    unsigned lanelt = (1u << (t & 31)) - 1u;
    if (cat == 0) {
        int ldr = __ffs(m0) - 1, bse = 0;
        if ((t & 31) == ldr) bse = atomicAdd(&place[0], __popc(m0));
        bse = __shfl_sync(m0, bse, ldr);
        int r = bse + __popc(m0 & lanelt);
        wl[r]      = (unsigned short)t;            // Blo entry (rank r)
        wl[nB + r] = (unsigned short)t;            // Bhi entry (pair)
    } else if (cat == 1) {
        int ldr = __ffs(m1) - 1, bse = 0;
        if ((t & 31) == ldr) bse = atomicAdd(&place[1], __popc(m1));
        bse = __shfl_sync(m1, bse, ldr);
        wl[bse + __popc(m1 & lanelt)] = (unsigned short)t;
    } else if (cat == 2) {
        int ldr = __ffs(m2) - 1, bse = 0;
        if ((t & 31) == ldr) bse = atomicAdd(&place[2], __popc(m2));
        bse = __shfl_sync(m2, bse, ldr);
        wl[bse + __popc(m2 & lanelt)] = (unsigned short)t;
    }
    __syncthreads();

    const int totalP = baseN + nN;                 // padded total

    for (int e = t; e < totalP; e += 256) {
        int lp = wl[e];
        bool active = (lp != (int)SENT);
        if (e < baseU) {
            // ---- B segment: both streams over half frame range ----
            if (active) {
                float4 v = stash[lp];
                float vb = v.x, vfw = v.y, vnfa = v.z, vgs = v.w;
                bool lo = (e < nB);
                int f0 = lo ? 0 : hf;
                int f1 = lo ? hf : nf;
                uint32_t j = (uint32_t)(b * FMAX) * (uint32_t)HW
                           + (uint32_t)(p0 + lp) + (uint32_t)f0 * (uint32_t)HW;
                float acc = 0.0f;
                for (int f = f0; f < f1; ++f, j += (uint32_t)HW) {
                    uint32_t ub = tf_xor(ku0, ku1, j);
                    uint32_t nb = tf_xor(kn0, kn1, j);
                    float s = fmaf(vfw, u_term(ub, vnfa), vb);
                    s = fmaf(vgs, n_term(nb), s);
                    acc += clip01(s);
                }
                if (lo) partA[e] = acc; else partB[e - nB] = acc;
            }
        } else if (e < baseN) {
            // ---- U segment: uniform-only, full range ----
            if (active) {
                float4 v = stash[lp];
                float vb = v.x, vfw = v.y, vnfa = v.z;
                uint32_t j = (uint32_t)(b * FMAX) * (uint32_t)HW + (uint32_t)(p0 + lp);
                float acc = 0.0f;
                for (int f = 0; f < nf; ++f, j += (uint32_t)HW) {
                    uint32_t u0 = tf_xor(ku0, ku1, j);
                    acc += clip01(fmaf(vfw, u_term(u0, vnfa), vb));
                }
                out[gpix + lp] = acc / (float)nf;
            }
        } else {
            // ---- N segment: normal-only, full range ----
            if (active) {
                float4 v = stash[lp];
                float vb = v.x, vgs = v.w;
                uint32_t j = (uint32_t)(b * FMAX) * (uint32_t)HW + (uint32_t)(p0 + lp);
                float acc = 0.0f;
                for (int f = 0; f < nf; ++f, j += (uint32_t)HW) {
                    uint32_t n0 = tf_xor(kn0, kn1, j);
                    acc += clip01(fmaf(vgs, n_term(n0), vb));
                }
                out[gpix + lp] = acc / (float)nf;
            }
        }
    }

    __syncthreads();

    for (int i = t; i < nB; i += 256) {
        int lp = wl[i];
        out[gpix + lp] = (partA[i] + partB[i]) / (float)nf;
    }
}

// ---------------------------------------------------------------------------
// Host-side threefry for key derivation from jax.random.key(42)
// ---------------------------------------------------------------------------
static inline uint32_t h_rotl(uint32_t x, int r) { return (x << r) | (x >> (32 - r)); }
static void h_tf2x32(uint32_t k0, uint32_t k1, uint32_t x0, uint32_t x1,
                     uint32_t& o0, uint32_t& o1) {
    uint32_t k2 = k0 ^ k1 ^ 0x1BD11BDAu;
    x0 += k0; x1 += k1;
#define HTFR(r) { x0 += x1; x1 = h_rotl(x1, (r)); x1 ^= x0; }
    HTFR(13) HTFR(15) HTFR(26) HTFR(6)   x0 += k1; x1 += k2 + 1u;
    HTFR(17) HTFR(29) HTFR(16) HTFR(24)  x0 += k2; x1 += k0 + 2u;
    HTFR(13) HTFR(15) HTFR(26) HTFR(6)   x0 += k0; x1 += k1 + 3u;
    HTFR(17) HTFR(29) HTFR(16) HTFR(24)  x0 += k1; x1 += k2 + 4u;
    HTFR(13) HTFR(15) HTFR(26) HTFR(6)   x0 += k2; x1 += k0 + 5u;
#undef HTFR
    o0 = x0; o1 = x1;
}

extern "C" void kernel_launch(void* const* d_in, const int* in_sizes, int n_in,
                              void* d_out, int out_size) {
    const float* inp    = (const float*)d_in[0];
    const int*   frames = (const int*)d_in[1];
    float*       out    = (float*)d_out;

    uint32_t ku0, ku1, kn0, kn1;
    h_tf2x32(0u, 42u, 0u, 0u, ku0, ku1);
    h_tf2x32(0u, 42u, 0u, 1u, kn0, kn1);

    bias_partial<<<512, 256>>>(inp);
    bias_final<<<1, 256>>>();
    acq_kernel<<<NPIX / 256, 256>>>(inp, frames, out, ku0, ku1, kn0, kn1);
}

// round 11
// speedup vs baseline: 1.1604x; 1.0277x over previous
#include <cuda_runtime.h>
#include <cstdint>

// JAX threefry (partitionable), bit-exact draws confirmed (rel_err ~5e-8).
// R10: warp-aligned worklist segments (103.1us, confirmed divergence cost).
// R11: branchless n_term — both erfinv polynomial branches computed
//      unconditionally + FSEL. Removes BSSY/BSYNC (~33-56cyc, per
//      SASS_QUICKREF) paid on EVERY n_term call, plus the ~10%-of-warps
//      real divergence where both bodies serialized.

static constexpr int Bn   = 8;
static constexpr int Cn   = 5;
static constexpr int FMAX = 16;
static constexpr int HW   = 512 * 512;        // 2^18
static constexpr int NPIX = Bn * HW;          // 2^21
static constexpr unsigned short SENT = 0xFFFFu;

__device__ float g_bias[Bn];
__device__ float g_part[512];

// ---------------------------------------------------------------------------
__device__ __forceinline__ float f_lg2(float x) { float r; asm("lg2.approx.f32 %0,%1;"  : "=f"(r) : "f"(x)); return r; }
__device__ __forceinline__ float f_ex2(float x) { float r; asm("ex2.approx.f32 %0,%1;"  : "=f"(r) : "f"(x)); return r; }
__device__ __forceinline__ float f_sqa(float x) { float r; asm("sqrt.approx.f32 %0,%1;" : "=f"(r) : "f"(x)); return r; }
__device__ __forceinline__ float clip01(float x) { return fminf(fmaxf(x, 0.0f), 1.0f); }

// Threefry-2x32, 20 rounds; counter (0, j); returns x0 ^ x1 (partitionable fold)
__device__ __forceinline__ uint32_t tf_xor(uint32_t k0, uint32_t k1, uint32_t j) {
    uint32_t k2 = k0 ^ k1 ^ 0x1BD11BDAu;
    uint32_t x0 = k0;
    uint32_t x1 = j + k1;
#define TFR(r) { x0 += x1; x1 = __funnelshift_l(x1, x1, (r)); x1 ^= x0; }
    TFR(13) TFR(15) TFR(26) TFR(6)   x0 += k1; x1 += k2 + 1u;
    TFR(17) TFR(29) TFR(16) TFR(24)  x0 += k2; x1 += k0 + 2u;
    TFR(13) TFR(15) TFR(26) TFR(6)   x0 += k0; x1 += k1 + 3u;
    TFR(17) TFR(29) TFR(16) TFR(24)  x0 += k1; x1 += k2 + 4u;
    TFR(13) TFR(15) TFR(26) TFR(6)   x0 += k2; x1 += k0 + 5u;
#undef TFR
    return x0 ^ x1;
}

// uniform-bits -> (-log u)^(-fa)  (bit-validated R3/R5; fully branchless)
__device__ __forceinline__ float u_term(uint32_t ub, float nfa) {
    float su = (float)(ub >> 9);
    float u  = su * 1.1920928955078125e-7f;            // * 2^-23 exact
    u = fminf(fmaxf(u, 1e-6f), 0.999999f);
    float tA = f_lg2(u) * -0.693147180559945f;         // MUFU path
    float v  = u - 1.0f;                               // exact for u >= 0.5
    float P  = fmaf(v, 0.14285714f, -0.16666667f);
    P = fmaf(P, v, 0.20f);
    P = fmaf(P, v, -0.25f);
    P = fmaf(P, v, 0.33333333f);
    P = fmaf(P, v, -0.5f);
    P = fmaf(P, v, 1.0f);
    float tB = -(v * P);                               // log1p Taylor near 1
    float t  = (u >= 0.875f) ? tB : tA;
    return f_ex2(nfa * f_lg2(t));                      // t^(-fa)
}

// normal-bits -> erfinv(g); caller supplies sqrt(2) inside vgs = gw*sqrt2.
// BRANCHLESS: both Giles polynomial branches evaluated, FSEL at the end.
// The two 9-FMA chains are independent -> dual-issue ILP; no BSSY/BSYNC.
__device__ __forceinline__ float n_term(uint32_t nb) {
    const float LO = -0.99999994f;                     // nextafter(-1, 0)
    float sn = (float)(nb >> 9);
    float gx = fmaf(sn, 2.384185791015625e-7f, LO);    // * 2^-22 exact
    float W  = f_lg2(fmaf(-gx, gx, 1.0f));             // lg2(1-gx^2), <= 0
    float w  = W * -0.693147180559945f;                // -ln(1-gx^2) >= 0

    // central branch: z1 = w - 2.5
    float z1 = w - 2.5f;
    float pa = 2.81022636e-08f;
    pa = fmaf(pa, z1, 3.43273939e-07f);
    pa = fmaf(pa, z1, -3.5233877e-06f);
    pa = fmaf(pa, z1, -4.39150654e-06f);
    pa = fmaf(pa, z1, 0.00021858087f);
    pa = fmaf(pa, z1, -0.00125372503f);
    pa = fmaf(pa, z1, -0.00417768164f);
    pa = fmaf(pa, z1, 0.246640727f);
    pa = fmaf(pa, z1, 1.50140941f);

    // tail branch: z2 = sqrt(w) - 3  (independent chain)
    float z2 = f_sqa(w) - 3.0f;
    float pb = -0.000200214257f;
    pb = fmaf(pb, z2, 0.000100950558f);
    pb = fmaf(pb, z2, 0.00134934322f);
    pb = fmaf(pb, z2, -0.00367342844f);
    pb = fmaf(pb, z2, 0.00573950773f);
    pb = fmaf(pb, z2, -0.0076224613f);
    pb = fmaf(pb, z2, 0.00943887047f);
    pb = fmaf(pb, z2, 1.00167406f);
    pb = fmaf(pb, z2, 2.83297682f);

    float pe = (w < 5.0f) ? pa : pb;
    return pe * gx;                                    // erfinv(gx)
}

// ---------------------------------------------------------------------------
// Bias stage 1: 512 blocks (64/batch) x 256 threads, 4 strided float4 (MLP=4)
// ---------------------------------------------------------------------------
__global__ void __launch_bounds__(256) bias_partial(const float* __restrict__ in) {
    int b     = blockIdx.x >> 6;
    int chunk = blockIdx.x & 63;
    int t     = threadIdx.x;
    const float4* p4 = reinterpret_cast<const float4*>(in + ((size_t)b * Cn + 1) * HW)
                     + (size_t)chunk * 1024;
    float4 a = p4[t], b4 = p4[t + 256], c = p4[t + 512], d = p4[t + 768];
    float s = ((a.x + a.y) + (a.z + a.w)) + ((b4.x + b4.y) + (b4.z + b4.w))
            + ((c.x + c.y) + (c.z + c.w)) + ((d.x + d.y) + (d.z + d.w));
    __shared__ float sm[8];
    #pragma unroll
    for (int o = 16; o > 0; o >>= 1) s += __shfl_down_sync(0xffffffffu, s, o);
    if ((t & 31) == 0) sm[t >> 5] = s;
    __syncthreads();
    if (t == 0) {
        float acc = 0.0f;
        #pragma unroll
        for (int k = 0; k < 8; k++) acc += sm[k];
        g_part[blockIdx.x] = acc;
    }
}

// Bias stage 2: one block; warp b reduces its 64 partials in fixed order
__global__ void __launch_bounds__(256) bias_final() {
    int b = threadIdx.x >> 5, l = threadIdx.x & 31;
    float v = g_part[b * 64 + l] + g_part[b * 64 + 32 + l];
    #pragma unroll
    for (int o = 16; o > 0; o >>= 1) v += __shfl_down_sync(0xffffffffu, v, o);
    if (l == 0) g_bias[b] = fmaxf(v * (1.0f / (float)HW), 0.0f);
}

// ---------------------------------------------------------------------------
// Main kernel: classify -> warp-aligned compaction -> one body per warp
// Layout: [B: 0..2nB) | pad | U: baseU..baseU+nU) | pad | N: baseN..baseN+nN)
// ---------------------------------------------------------------------------
__global__ void __launch_bounds__(256)
acq_kernel(const float* __restrict__ in, const int* __restrict__ frames,
           float* __restrict__ out,
           uint32_t ku0, uint32_t ku1, uint32_t kn0, uint32_t kn1) {
    __shared__ float4 stash[256];
    __shared__ unsigned short wl[576];
    __shared__ float partA[256];
    __shared__ float partB[256];
    __shared__ int segcnt[3];   // [B, U, N]
    __shared__ int place[3];

    const int t     = threadIdx.x;
    const int b     = blockIdx.x & 7;              // batch-interleaved remap
    const int chunk = blockIdx.x >> 3;
    const int p0    = chunk * 256;                 // pixel base within batch
    const int gpix  = b * HW + p0;

    const float* base = in + (size_t)b * Cn * HW + (p0 + t);
    float img = base[0];
    float fw  = fmaxf(base[2 * HW], 0.0f);
    float fa  = fmaxf(base[3 * HW], 0.0f);
    float gw  = fmaxf(base[4 * HW], 0.0f);
    float bias = g_bias[b];
    const int nf = frames[b];                      // uniform across block
    const int hf = (nf + 1) >> 1;                  // frame split point

    float cb  = img + bias;
    float nfa = -fa;
    float gs  = gw * 1.41421356237f;               // gw * sqrt(2)

    // center (all pixels)
    float cpw = f_ex2(nfa * f_lg2(fa + 1.0f));
    out[NPIX + gpix + t] = clip01(fmaf(fw, cpw, cb));

    // classification
    bool needU = (fw > 0.0f) && (fa > 0.0f);
    bool needN = (gw > 0.0f);
    int  cat   = needU ? (needN ? 0 : 1) : (needN ? 2 : 3);
    float cbase = (cat >= 2) ? (cb + ((fa == 0.0f) ? fw : 0.0f)) : cb;

    if (cat == 3) out[gpix + t] = clip01(cbase);   // deterministic: done

    stash[t] = make_float4(cbase, fw, nfa, gs);

    // clear sentinel worklist (576 entries)
    wl[t] = SENT; wl[t + 256] = SENT;
    if (t < 64) wl[t + 512] = SENT;
    if (t < 3) segcnt[t] = 0;
    __syncthreads();

    unsigned m0 = __ballot_sync(0xffffffffu, cat == 0);
    unsigned m1 = __ballot_sync(0xffffffffu, cat == 1);
    unsigned m2 = __ballot_sync(0xffffffffu, cat == 2);
    if ((t & 31) == 0) {
        if (m0) atomicAdd(&segcnt[0], __popc(m0));
        if (m1) atomicAdd(&segcnt[1], __popc(m1));
        if (m2) atomicAdd(&segcnt[2], __popc(m2));
    }
    __syncthreads();
    const int nB = segcnt[0], nU = segcnt[1], nN = segcnt[2];
    const int baseU = (2 * nB + 31) & ~31;         // warp-aligned U base
    const int baseN = (baseU + nU + 31) & ~31;     // warp-aligned N base
    if (t == 0) {
        place[0] = 0;
        place[1] = baseU;
        place[2] = baseN;
    }
    __syncthreads();

    unsigned lanelt = (1u << (t & 31)) - 1u;
    if (cat == 0) {
        int ldr = __ffs(m0) - 1, bse = 0;
        if ((t & 31) == ldr) bse = atomicAdd(&place[0], __popc(m0));
        bse = __shfl_sync(m0, bse, ldr);
        int r = bse + __popc(m0 & lanelt);
        wl[r]      = (unsigned short)t;            // Blo entry (rank r)
        wl[nB + r] = (unsigned short)t;            // Bhi entry (pair)
    } else if (cat == 1) {
        int ldr = __ffs(m1) - 1, bse = 0;
        if ((t & 31) == ldr) bse = atomicAdd(&place[1], __popc(m1));
        bse = __shfl_sync(m1, bse, ldr);
        wl[bse + __popc(m1 & lanelt)] = (unsigned short)t;
    } else if (cat == 2) {
        int ldr = __ffs(m2) - 1, bse = 0;
        if ((t & 31) == ldr) bse = atomicAdd(&place[2], __popc(m2));
        bse = __shfl_sync(m2, bse, ldr);
        wl[bse + __popc(m2 & lanelt)] = (unsigned short)t;
    }
    __syncthreads();

    const int totalP = baseN + nN;                 // padded total

    for (int e = t; e < totalP; e += 256) {
        int lp = wl[e];
        bool active = (lp != (int)SENT);
        if (e < baseU) {
            // ---- B segment: both streams over half frame range ----
            if (active) {
                float4 v = stash[lp];
                float vb = v.x, vfw = v.y, vnfa = v.z, vgs = v.w;
                bool lo = (e < nB);
                int f0 = lo ? 0 : hf;
                int f1 = lo ? hf : nf;
                uint32_t j = (uint32_t)(b * FMAX) * (uint32_t)HW
                           + (uint32_t)(p0 + lp) + (uint32_t)f0 * (uint32_t)HW;
                float acc = 0.0f;
                for (int f = f0; f < f1; ++f, j += (uint32_t)HW) {
                    uint32_t ub = tf_xor(ku0, ku1, j);
                    uint32_t nb = tf_xor(kn0, kn1, j);
                    float s = fmaf(vfw, u_term(ub, vnfa), vb);
                    s = fmaf(vgs, n_term(nb), s);
                    acc += clip01(s);
                }
                if (lo) partA[e] = acc; else partB[e - nB] = acc;
            }
        } else if (e < baseN) {
            // ---- U segment: uniform-only, full range ----
            if (active) {
                float4 v = stash[lp];
                float vb = v.x, vfw = v.y, vnfa = v.z;
                uint32_t j = (uint32_t)(b * FMAX) * (uint32_t)HW + (uint32_t)(p0 + lp);
                float acc = 0.0f;
                for (int f = 0; f < nf; ++f, j += (uint32_t)HW) {
                    uint32_t u0 = tf_xor(ku0, ku1, j);
                    acc += clip01(fmaf(vfw, u_term(u0, vnfa), vb));
                }
                out[gpix + lp] = acc / (float)nf;
            }
        } else {
            // ---- N segment: normal-only, full range ----
            if (active) {
                float4 v = stash[lp];
                float vb = v.x, vgs = v.w;
                uint32_t j = (uint32_t)(b * FMAX) * (uint32_t)HW + (uint32_t)(p0 + lp);
                float acc = 0.0f;
                for (int f = 0; f < nf; ++f, j += (uint32_t)HW) {
                    uint32_t n0 = tf_xor(kn0, kn1, j);
                    acc += clip01(fmaf(vgs, n_term(n0), vb));
                }
                out[gpix + lp] = acc / (float)nf;
            }
        }
    }

    __syncthreads();

    for (int i = t; i < nB; i += 256) {
        int lp = wl[i];
        out[gpix + lp] = (partA[i] + partB[i]) / (float)nf;
    }
}

// ---------------------------------------------------------------------------
// Host-side threefry for key derivation from jax.random.key(42)
// ---------------------------------------------------------------------------
static inline uint32_t h_rotl(uint32_t x, int r) { return (x << r) | (x >> (32 - r)); }
static void h_tf2x32(uint32_t k0, uint32_t k1, uint32_t x0, uint32_t x1,
                     uint32_t& o0, uint32_t& o1) {
    uint32_t k2 = k0 ^ k1 ^ 0x1BD11BDAu;
    x0 += k0; x1 += k1;
#define HTFR(r) { x0 += x1; x1 = h_rotl(x1, (r)); x1 ^= x0; }
    HTFR(13) HTFR(15) HTFR(26) HTFR(6)   x0 += k1; x1 += k2 + 1u;
    HTFR(17) HTFR(29) HTFR(16) HTFR(24)  x0 += k2; x1 += k0 + 2u;
    HTFR(13) HTFR(15) HTFR(26) HTFR(6)   x0 += k0; x1 += k1 + 3u;
    HTFR(17) HTFR(29) HTFR(16) HTFR(24)  x0 += k1; x1 += k2 + 4u;
    HTFR(13) HTFR(15) HTFR(26) HTFR(6)   x0 += k2; x1 += k0 + 5u;
#undef HTFR
    o0 = x0; o1 = x1;
}

extern "C" void kernel_launch(void* const* d_in, const int* in_sizes, int n_in,
                              void* d_out, int out_size) {
    const float* inp    = (const float*)d_in[0];
    const int*   frames = (const int*)d_in[1];
    float*       out    = (float*)d_out;

    uint32_t ku0, ku1, kn0, kn1;
    h_tf2x32(0u, 42u, 0u, 0u, ku0, ku1);
    h_tf2x32(0u, 42u, 0u, 1u, kn0, kn1);

    bias_partial<<<512, 256>>>(inp);
    bias_final<<<1, 256>>>();
    acq_kernel<<<NPIX / 256, 256>>>(inp, frames, out, ku0, ku1, kn0, kn1);
}